// round 3
// baseline (speedup 1.0000x reference)
#include <cuda_runtime.h>
#include <cuda_bf16.h>
#include <cstdint>
#include <cstddef>

#define TOK  4096          // B*S tokens
#define DIM  1024          // D
#define HID  2816          // H
#define NEXP 8             // experts
#define NROW (2 * TOK)     // total gathered rows (top-2, distinct experts)

// ---------------- scratch (static device arrays; ~96 MB total) -------------
__device__ float        g_xn[TOK * DIM];       // rms-normed activations (16.8 MB)
__device__ __nv_bfloat16 g_hact[NROW * HID];   // swiglu output, gathered rows (46 MB)
__device__ float        g_y[NROW * DIM];       // down output, gathered rows (33.5 MB)
__device__ int   g_cnt[NEXP];                  // per-expert row counts
__device__ int   g_off[NEXP];                  // exclusive prefix offsets
__device__ int   g_cur[NEXP];                  // scatter cursors
__device__ int   g_eid[TOK * 2];               // top-2 expert ids per token
__device__ float g_coef[TOK * 2];              // softmax prob per (token, k)
__device__ int   g_tok[NROW];                  // token index per gathered row
__device__ int   g_rowof[TOK * 2];             // gathered-row index per (token, k)

// ---------------- helpers --------------------------------------------------
__device__ __forceinline__ unsigned f2tf(float f) {
    unsigned u;
    asm("cvt.rna.tf32.f32 %0, %1;" : "=r"(u) : "f"(f));
    return u;
}

__device__ __forceinline__ void mma8(float d[4], const unsigned a[4], const unsigned b[2]) {
    asm volatile(
        "mma.sync.aligned.m16n8k8.row.col.f32.tf32.tf32.f32 "
        "{%0,%1,%2,%3}, {%4,%5,%6,%7}, {%8,%9}, {%0,%1,%2,%3};\n"
        : "+f"(d[0]), "+f"(d[1]), "+f"(d[2]), "+f"(d[3])
        : "r"(a[0]), "r"(a[1]), "r"(a[2]), "r"(a[3]),
          "r"(b[0]), "r"(b[1]));
}

// ---------------- kernel 0: zero counters ----------------------------------
__global__ void zero_cnt_kernel() {
    if (threadIdx.x < NEXP) {
        g_cnt[threadIdx.x] = 0;
        g_cur[threadIdx.x] = 0;
    }
}

// ---------------- kernel 1: rmsnorm + router + top2 ------------------------
__global__ void __launch_bounds__(256) phase1_kernel(
    const float* __restrict__ x,
    const float* __restrict__ scale,
    const float* __restrict__ wr)
{
    __shared__ float s_xn[DIM];
    __shared__ float s_red[8];
    __shared__ float s_sc[8];
    __shared__ float s_r;

    const int t = blockIdx.x;
    const int tid = threadIdx.x;
    const int lane = tid & 31;
    const int w = tid >> 5;

    float4 xv = *(const float4*)(x + (size_t)t * DIM + tid * 4);
    float ss = xv.x * xv.x + xv.y * xv.y + xv.z * xv.z + xv.w * xv.w;
    #pragma unroll
    for (int o = 16; o; o >>= 1) ss += __shfl_xor_sync(0xffffffffu, ss, o);
    if (lane == 0) s_red[w] = ss;
    __syncthreads();
    if (tid == 0) {
        float tot = 0.f;
        #pragma unroll
        for (int i = 0; i < 8; i++) tot += s_red[i];
        s_r = rsqrtf(tot / (float)DIM + 1e-6f);
    }
    __syncthreads();
    const float r = s_r;

    float4 sc = *(const float4*)(scale + tid * 4);
    float4 xn;
    xn.x = xv.x * sc.x * r;
    xn.y = xv.y * sc.y * r;
    xn.z = xv.z * sc.z * r;
    xn.w = xv.w * sc.w * r;
    *(float4*)(&s_xn[tid * 4]) = xn;
    *(float4*)(g_xn + (size_t)t * DIM + tid * 4) = xn;
    __syncthreads();

    // router: warp w computes expert w's score
    float acc = 0.f;
    const float* wre = wr + (size_t)w * DIM;
    for (int i = lane; i < DIM; i += 32) acc += s_xn[i] * wre[i];
    #pragma unroll
    for (int o = 16; o; o >>= 1) acc += __shfl_xor_sync(0xffffffffu, acc, o);
    if (lane == 0) s_sc[w] = acc;
    __syncthreads();

    if (tid == 0) {
        float s[NEXP];
        #pragma unroll
        for (int e = 0; e < NEXP; e++) s[e] = s_sc[e];
        int i0 = 0;
        #pragma unroll
        for (int e = 1; e < NEXP; e++) if (s[e] > s[i0]) i0 = e;
        int i1 = (i0 == 0) ? 1 : 0;
        #pragma unroll
        for (int e = 0; e < NEXP; e++) if (e != i0 && s[e] > s[i1]) i1 = e;
        const float mx = s[i0];
        float sum = 0.f;
        #pragma unroll
        for (int e = 0; e < NEXP; e++) sum += expf(s[e] - mx);
        g_eid[2 * t + 0] = i0;
        g_eid[2 * t + 1] = i1;
        g_coef[2 * t + 0] = 1.0f / sum;
        g_coef[2 * t + 1] = expf(s[i1] - mx) / sum;
        atomicAdd(&g_cnt[i0], 1);
        atomicAdd(&g_cnt[i1], 1);
    }
}

// ---------------- kernel 2: exclusive prefix over 8 counts -----------------
__global__ void offsets_kernel() {
    if (threadIdx.x == 0) {
        int acc = 0;
        #pragma unroll
        for (int e = 0; e < NEXP; e++) { g_off[e] = acc; acc += g_cnt[e]; }
    }
}

// ---------------- kernel 3: scatter tokens to gathered rows ----------------
__global__ void __launch_bounds__(256) scatter_kernel() {
    const int t = blockIdx.x * 256 + threadIdx.x;
    if (t >= TOK) return;
    #pragma unroll
    for (int k = 0; k < 2; k++) {
        int e = g_eid[2 * t + k];
        int row = g_off[e] + atomicAdd(&g_cur[e], 1);
        g_tok[row] = t;
        g_rowof[2 * t + k] = row;
    }
}

// ---------------- kernel 4: grouped up-GEMM + fused swiglu -----------------
// C_val[i][j] = dot(xn[tok_i], w_up[e][j]),  C_gate with column j+H
// h = val * silu(gate) -> g_hact (bf16)
__global__ void __launch_bounds__(128) up_kernel(const float* __restrict__ w_up) {
    const int e    = blockIdx.z;
    const int M    = g_cnt[e];
    const int m0   = blockIdx.y * 64;
    if (m0 >= M) return;
    const int base = g_off[e];
    const int jt   = blockIdx.x;               // 0 .. HID/64-1

    __shared__ unsigned sA[64 * 36];
    __shared__ unsigned sBv[64 * 36];
    __shared__ unsigned sBg[64 * 36];
    __shared__ int s_rows[64];

    const int tid  = threadIdx.x;
    const int lane = tid & 31;
    const int warp = tid >> 5;
    const int wm = warp >> 1, wn = warp & 1;
    const int g = lane >> 2, l = lane & 3;

    if (tid < 64) {
        int m = m0 + tid;
        s_rows[tid] = (m < M) ? g_tok[base + m] : -1;
    }
    __syncthreads();

    const float* Bv = w_up + (size_t)e * (2 * HID) * DIM + (size_t)(jt * 64) * DIM;
    const float* Bg = Bv + (size_t)HID * DIM;

    int lrow[4], lc4[4];
    #pragma unroll
    for (int p = 0; p < 4; p++) {
        int idx = p * 128 + tid;
        lrow[p] = idx >> 3;
        lc4[p]  = (idx & 7) << 2;
    }
    int arow[4];
    #pragma unroll
    for (int p = 0; p < 4; p++) arow[p] = s_rows[lrow[p]];

    float accv[2][4][4] = {};
    float accg[2][4][4] = {};
    float4 rA[4], rBv[4], rBg[4];

    // prefetch k-tile 0
    #pragma unroll
    for (int p = 0; p < 4; p++) {
        rA[p]  = (arow[p] >= 0) ? *(const float4*)(g_xn + (size_t)arow[p] * DIM + lc4[p])
                                : make_float4(0.f, 0.f, 0.f, 0.f);
        rBv[p] = *(const float4*)(Bv + (size_t)lrow[p] * DIM + lc4[p]);
        rBg[p] = *(const float4*)(Bg + (size_t)lrow[p] * DIM + lc4[p]);
    }

    for (int k0 = 0; k0 < DIM; k0 += 32) {
        #pragma unroll
        for (int p = 0; p < 4; p++) {
            unsigned* pA = &sA [lrow[p] * 36 + lc4[p]];
            pA[0] = f2tf(rA[p].x); pA[1] = f2tf(rA[p].y); pA[2] = f2tf(rA[p].z); pA[3] = f2tf(rA[p].w);
            unsigned* pV = &sBv[lrow[p] * 36 + lc4[p]];
            pV[0] = f2tf(rBv[p].x); pV[1] = f2tf(rBv[p].y); pV[2] = f2tf(rBv[p].z); pV[3] = f2tf(rBv[p].w);
            unsigned* pG = &sBg[lrow[p] * 36 + lc4[p]];
            pG[0] = f2tf(rBg[p].x); pG[1] = f2tf(rBg[p].y); pG[2] = f2tf(rBg[p].z); pG[3] = f2tf(rBg[p].w);
        }
        __syncthreads();

        // prefetch next k-tile (overlaps with MMAs)
        const int kn = k0 + 32;
        if (kn < DIM) {
            #pragma unroll
            for (int p = 0; p < 4; p++) {
                rA[p]  = (arow[p] >= 0) ? *(const float4*)(g_xn + (size_t)arow[p] * DIM + kn + lc4[p])
                                        : make_float4(0.f, 0.f, 0.f, 0.f);
                rBv[p] = *(const float4*)(Bv + (size_t)lrow[p] * DIM + kn + lc4[p]);
                rBg[p] = *(const float4*)(Bg + (size_t)lrow[p] * DIM + kn + lc4[p]);
            }
        }

        #pragma unroll
        for (int ks = 0; ks < 4; ks++) {
            const int k8 = ks * 8;
            unsigned a[2][4];
            #pragma unroll
            for (int sm = 0; sm < 2; sm++) {
                int rb = wm * 32 + sm * 16;
                a[sm][0] = sA[(rb + g    ) * 36 + k8 + l    ];
                a[sm][1] = sA[(rb + g + 8) * 36 + k8 + l    ];
                a[sm][2] = sA[(rb + g    ) * 36 + k8 + l + 4];
                a[sm][3] = sA[(rb + g + 8) * 36 + k8 + l + 4];
            }
            #pragma unroll
            for (int sn = 0; sn < 4; sn++) {
                int cb = wn * 32 + sn * 8;
                unsigned fv[2], fg[2];
                fv[0] = sBv[(cb + g) * 36 + k8 + l    ];
                fv[1] = sBv[(cb + g) * 36 + k8 + l + 4];
                fg[0] = sBg[(cb + g) * 36 + k8 + l    ];
                fg[1] = sBg[(cb + g) * 36 + k8 + l + 4];
                mma8(accv[0][sn], a[0], fv);
                mma8(accv[1][sn], a[1], fv);
                mma8(accg[0][sn], a[0], fg);
                mma8(accg[1][sn], a[1], fg);
            }
        }
        __syncthreads();
    }

    // epilogue: h = val * silu(gate), store bf16
    #pragma unroll
    for (int sm = 0; sm < 2; sm++) {
        #pragma unroll
        for (int sn = 0; sn < 4; sn++) {
            #pragma unroll
            for (int c = 0; c < 4; c++) {
                int row = wm * 32 + sm * 16 + g + ((c >> 1) << 3);
                int col = wn * 32 + sn * 8 + (l << 1) + (c & 1);
                if (m0 + row < M) {
                    float v  = accv[sm][sn][c];
                    float gt = accg[sm][sn][c];
                    float h  = v * (gt / (1.f + __expf(-gt)));
                    g_hact[(size_t)(base + m0 + row) * HID + jt * 64 + col] = __float2bfloat16(h);
                }
            }
        }
    }
}

// ---------------- kernel 5: grouped down-GEMM ------------------------------
__global__ void __launch_bounds__(128) down_kernel(const float* __restrict__ w_down) {
    const int e    = blockIdx.z;
    const int M    = g_cnt[e];
    const int m0   = blockIdx.y * 64;
    if (m0 >= M) return;
    const int base = g_off[e];
    const int jt   = blockIdx.x;               // 0 .. DIM/64-1

    __shared__ unsigned sA[64 * 36];
    __shared__ unsigned sB[64 * 36];

    const int tid  = threadIdx.x;
    const int lane = tid & 31;
    const int warp = tid >> 5;
    const int wm = warp >> 1, wn = warp & 1;
    const int g = lane >> 2, l = lane & 3;

    const float* Bp = w_down + (size_t)e * DIM * HID + (size_t)(jt * 64) * HID;
    const __nv_bfloat16* Ap = g_hact + (size_t)(base + m0) * HID;
    const int mrem = M - m0;

    int lrow[4], lc4[4];
    #pragma unroll
    for (int p = 0; p < 4; p++) {
        int idx = p * 128 + tid;
        lrow[p] = idx >> 3;
        lc4[p]  = (idx & 7) << 2;
    }

    float acc[2][4][4] = {};
    float4  rB[4];
    // A loads: 4 bf16 = 8 bytes per slice
    uint2 rA[4];

    #pragma unroll
    for (int p = 0; p < 4; p++) {
        rA[p] = (lrow[p] < mrem) ? *(const uint2*)(Ap + (size_t)lrow[p] * HID + lc4[p])
                                 : make_uint2(0u, 0u);
        rB[p] = *(const float4*)(Bp + (size_t)lrow[p] * HID + lc4[p]);
    }

    for (int k0 = 0; k0 < HID; k0 += 32) {
        #pragma unroll
        for (int p = 0; p < 4; p++) {
            const __nv_bfloat162 h0 = *(const __nv_bfloat162*)&rA[p].x;
            const __nv_bfloat162 h1 = *(const __nv_bfloat162*)&rA[p].y;
            unsigned* pA = &sA[lrow[p] * 36 + lc4[p]];
            pA[0] = f2tf(__bfloat162float(h0.x));
            pA[1] = f2tf(__bfloat162float(h0.y));
            pA[2] = f2tf(__bfloat162float(h1.x));
            pA[3] = f2tf(__bfloat162float(h1.y));
            unsigned* pB = &sB[lrow[p] * 36 + lc4[p]];
            pB[0] = f2tf(rB[p].x); pB[1] = f2tf(rB[p].y); pB[2] = f2tf(rB[p].z); pB[3] = f2tf(rB[p].w);
        }
        __syncthreads();

        const int kn = k0 + 32;
        if (kn < HID) {
            #pragma unroll
            for (int p = 0; p < 4; p++) {
                rA[p] = (lrow[p] < mrem) ? *(const uint2*)(Ap + (size_t)lrow[p] * HID + kn + lc4[p])
                                         : make_uint2(0u, 0u);
                rB[p] = *(const float4*)(Bp + (size_t)lrow[p] * HID + kn + lc4[p]);
            }
        }

        #pragma unroll
        for (int ks = 0; ks < 4; ks++) {
            const int k8 = ks * 8;
            unsigned a[2][4];
            #pragma unroll
            for (int sm = 0; sm < 2; sm++) {
                int rb = wm * 32 + sm * 16;
                a[sm][0] = sA[(rb + g    ) * 36 + k8 + l    ];
                a[sm][1] = sA[(rb + g + 8) * 36 + k8 + l    ];
                a[sm][2] = sA[(rb + g    ) * 36 + k8 + l + 4];
                a[sm][3] = sA[(rb + g + 8) * 36 + k8 + l + 4];
            }
            #pragma unroll
            for (int sn = 0; sn < 4; sn++) {
                int cb = wn * 32 + sn * 8;
                unsigned fb[2];
                fb[0] = sB[(cb + g) * 36 + k8 + l    ];
                fb[1] = sB[(cb + g) * 36 + k8 + l + 4];
                mma8(acc[0][sn], a[0], fb);
                mma8(acc[1][sn], a[1], fb);
            }
        }
        __syncthreads();
    }

    #pragma unroll
    for (int sm = 0; sm < 2; sm++) {
        #pragma unroll
        for (int sn = 0; sn < 4; sn++) {
            #pragma unroll
            for (int c = 0; c < 4; c++) {
                int row = wm * 32 + sm * 16 + g + ((c >> 1) << 3);
                int col = wn * 32 + sn * 8 + (l << 1) + (c & 1);
                if (m0 + row < M) {
                    g_y[(size_t)(base + m0 + row) * DIM + jt * 64 + col] = acc[sm][sn][c];
                }
            }
        }
    }
}

// ---------------- kernel 6: combine + skip ---------------------------------
__global__ void __launch_bounds__(256) combine_kernel(
    const float* __restrict__ x, float* __restrict__ out)
{
    const int t = blockIdx.x;
    const int r0 = g_rowof[2 * t + 0];
    const int r1 = g_rowof[2 * t + 1];
    const float c0 = g_coef[2 * t + 0];
    const float c1 = g_coef[2 * t + 1];
    const int i = threadIdx.x * 4;

    float4 xv = *(const float4*)(x   + (size_t)t  * DIM + i);
    float4 y0 = *(const float4*)(g_y + (size_t)r0 * DIM + i);
    float4 y1 = *(const float4*)(g_y + (size_t)r1 * DIM + i);
    float4 o;
    o.x = xv.x + c0 * y0.x + c1 * y1.x;
    o.y = xv.y + c0 * y0.y + c1 * y1.y;
    o.z = xv.z + c0 * y0.z + c1 * y1.z;
    o.w = xv.w + c0 * y0.w + c1 * y1.w;
    *(float4*)(out + (size_t)t * DIM + i) = o;
}

// ---------------- launch ---------------------------------------------------
extern "C" void kernel_launch(void* const* d_in, const int* in_sizes, int n_in,
                              void* d_out, int out_size) {
    (void)in_sizes; (void)n_in; (void)out_size;
    const float* x     = (const float*)d_in[0];   // [2,2048,1024] -> [4096,1024]
    const float* scale = (const float*)d_in[1];   // [1024]
    const float* wr    = (const float*)d_in[2];   // [8,1024]
    const float* wup   = (const float*)d_in[3];   // [8,5632,1024]
    const float* wdn   = (const float*)d_in[4];   // [8,1024,2816]
    float* out = (float*)d_out;

    zero_cnt_kernel<<<1, 32>>>();
    phase1_kernel<<<TOK, 256>>>(x, scale, wr);
    offsets_kernel<<<1, 32>>>();
    scatter_kernel<<<(TOK + 255) / 256, 256>>>();
    up_kernel<<<dim3(HID / 64, TOK / 64, NEXP), 128>>>(wup);
    down_kernel<<<dim3(DIM / 64, TOK / 64, NEXP), 128>>>(wdn);
    combine_kernel<<<TOK, 256>>>(x, out);
}

// round 5
// speedup vs baseline: 1.3500x; 1.3500x over previous
#include <cuda_runtime.h>
#include <cuda_bf16.h>
#include <cstdint>
#include <cstddef>

#define TOK  4096          // B*S tokens
#define DIM  1024          // D
#define HID  2816          // H
#define NEXP 8             // experts
#define NROW (2 * TOK)     // total gathered rows (top-2, distinct experts)
#define SW   20            // smem row stride in b32 words (16 data + 4 pad)

// ---------------- scratch (static device arrays; ~88 MB total) -------------
__device__ __nv_bfloat16 g_xn[TOK * DIM];      // rms-normed activations (8.4 MB)
__device__ __nv_bfloat16 g_hact[NROW * HID];   // swiglu output, gathered rows (46 MB)
__device__ float        g_y[NROW * DIM];       // down output, gathered rows (33.5 MB)
__device__ int   g_cnt[NEXP];
__device__ int   g_off[NEXP];
__device__ int   g_cur[NEXP];
__device__ int   g_eid[TOK * 2];
__device__ float g_coef[TOK * 2];
__device__ int   g_tok[NROW];
__device__ int   g_rowof[TOK * 2];

// ---------------- helpers --------------------------------------------------
__device__ __forceinline__ unsigned pk(float lo, float hi) {
    __nv_bfloat162 b = __floats2bfloat162_rn(lo, hi);  // .x=lo,.y=hi (mem order)
    return *(unsigned*)&b;
}

__device__ __forceinline__ void mma16(float d[4], const unsigned a[4], const unsigned b[2]) {
    asm volatile(
        "mma.sync.aligned.m16n8k16.row.col.f32.bf16.bf16.f32 "
        "{%0,%1,%2,%3}, {%4,%5,%6,%7}, {%8,%9}, {%0,%1,%2,%3};\n"
        : "+f"(d[0]), "+f"(d[1]), "+f"(d[2]), "+f"(d[3])
        : "r"(a[0]), "r"(a[1]), "r"(a[2]), "r"(a[3]),
          "r"(b[0]), "r"(b[1]));
}

// ---------------- kernel 0: zero counters ----------------------------------
__global__ void zero_cnt_kernel() {
    if (threadIdx.x < NEXP) {
        g_cnt[threadIdx.x] = 0;
        g_cur[threadIdx.x] = 0;
    }
}

// ---------------- kernel 1: rmsnorm + router + top2 ------------------------
__global__ void __launch_bounds__(256) phase1_kernel(
    const float* __restrict__ x,
    const float* __restrict__ scale,
    const float* __restrict__ wr)
{
    __shared__ float s_xn[DIM];
    __shared__ float s_red[8];
    __shared__ float s_sc[8];
    __shared__ float s_r;

    const int t = blockIdx.x;
    const int tid = threadIdx.x;
    const int lane = tid & 31;
    const int w = tid >> 5;

    float4 xv = *(const float4*)(x + (size_t)t * DIM + tid * 4);
    float ss = xv.x * xv.x + xv.y * xv.y + xv.z * xv.z + xv.w * xv.w;
    #pragma unroll
    for (int o = 16; o; o >>= 1) ss += __shfl_xor_sync(0xffffffffu, ss, o);
    if (lane == 0) s_red[w] = ss;
    __syncthreads();
    if (tid == 0) {
        float tot = 0.f;
        #pragma unroll
        for (int i = 0; i < 8; i++) tot += s_red[i];
        s_r = rsqrtf(tot / (float)DIM + 1e-6f);
    }
    __syncthreads();
    const float r = s_r;

    float4 sc = *(const float4*)(scale + tid * 4);
    float4 xn;
    xn.x = xv.x * sc.x * r;
    xn.y = xv.y * sc.y * r;
    xn.z = xv.z * sc.z * r;
    xn.w = xv.w * sc.w * r;
    *(float4*)(&s_xn[tid * 4]) = xn;
    uint2 pr;
    pr.x = pk(xn.x, xn.y);
    pr.y = pk(xn.z, xn.w);
    *(uint2*)(g_xn + (size_t)t * DIM + tid * 4) = pr;
    __syncthreads();

    float acc = 0.f;
    const float* wre = wr + (size_t)w * DIM;
    for (int i = lane; i < DIM; i += 32) acc += s_xn[i] * wre[i];
    #pragma unroll
    for (int o = 16; o; o >>= 1) acc += __shfl_xor_sync(0xffffffffu, acc, o);
    if (lane == 0) s_sc[w] = acc;
    __syncthreads();

    if (tid == 0) {
        float s[NEXP];
        #pragma unroll
        for (int e = 0; e < NEXP; e++) s[e] = s_sc[e];
        int i0 = 0;
        #pragma unroll
        for (int e = 1; e < NEXP; e++) if (s[e] > s[i0]) i0 = e;
        int i1 = (i0 == 0) ? 1 : 0;
        #pragma unroll
        for (int e = 0; e < NEXP; e++) if (e != i0 && s[e] > s[i1]) i1 = e;
        const float mx = s[i0];
        float sum = 0.f;
        #pragma unroll
        for (int e = 0; e < NEXP; e++) sum += expf(s[e] - mx);
        g_eid[2 * t + 0] = i0;
        g_eid[2 * t + 1] = i1;
        g_coef[2 * t + 0] = 1.0f / sum;
        g_coef[2 * t + 1] = expf(s[i1] - mx) / sum;
        atomicAdd(&g_cnt[i0], 1);
        atomicAdd(&g_cnt[i1], 1);
    }
}

// ---------------- kernel 2: exclusive prefix over 8 counts -----------------
__global__ void offsets_kernel() {
    if (threadIdx.x == 0) {
        int acc = 0;
        #pragma unroll
        for (int e = 0; e < NEXP; e++) { g_off[e] = acc; acc += g_cnt[e]; }
    }
}

// ---------------- kernel 3: scatter tokens to gathered rows ----------------
__global__ void __launch_bounds__(256) scatter_kernel() {
    const int t = blockIdx.x * 256 + threadIdx.x;
    if (t >= TOK) return;
    #pragma unroll
    for (int k = 0; k < 2; k++) {
        int e = g_eid[2 * t + k];
        int row = g_off[e] + atomicAdd(&g_cur[e], 1);
        g_tok[row] = t;
        g_rowof[2 * t + k] = row;
    }
}

// ---------------- kernel 4: grouped up-GEMM + fused swiglu -----------------
// Tile: 128 rows x 64 cols (val) + 64 cols (gate), 256 threads, K-tile 32.
__global__ void __launch_bounds__(256) up_kernel(const float* __restrict__ w_up) {
    const int e    = blockIdx.z;
    const int M    = g_cnt[e];
    const int m0   = blockIdx.x * 128;            // m fastest-varying -> L2 reuse of B
    if (m0 >= M) return;
    const int base = g_off[e];
    const int jt   = blockIdx.y;                  // 0 .. HID/64-1

    __shared__ unsigned sA [128 * SW];
    __shared__ unsigned sBv[ 64 * SW];
    __shared__ unsigned sBg[ 64 * SW];
    __shared__ int s_rows[128];

    const int tid  = threadIdx.x;
    const int lane = tid & 31;
    const int warp = tid >> 5;
    const int wm = warp >> 1, wn = warp & 1;      // wm 0..3 (32 rows), wn 0..1 (32 cols)
    const int g = lane >> 2, l = lane & 3;

    if (tid < 128) {
        int m = m0 + tid;
        s_rows[tid] = (m < M) ? g_tok[base + m] : -1;
    }
    __syncthreads();

    const float* Bv = w_up + (size_t)e * (2 * HID) * DIM + (size_t)(jt * 64) * DIM;
    const float* Bg = Bv + (size_t)HID * DIM;

    // A slices: p=0..3, idx in [0,1024): row=idx>>3, 4 bf16 at col (idx&7)*4
    int arowi[4], acol[4], arow[4];
    #pragma unroll
    for (int p = 0; p < 4; p++) {
        int idx = p * 256 + tid;
        arowi[p] = idx >> 3;
        acol[p]  = (idx & 7) << 2;
        arow[p]  = s_rows[arowi[p]];
    }
    // B slices: p=0..1, idx in [0,512): row=idx>>3, 4 floats at col (idx&7)*4
    int brow[2], bcol[2];
    #pragma unroll
    for (int p = 0; p < 2; p++) {
        int idx = p * 256 + tid;
        brow[p] = idx >> 3;
        bcol[p] = (idx & 7) << 2;
    }

    float accv[2][4][4] = {};
    float accg[2][4][4] = {};
    uint2  rA[4];
    float4 rBv[2], rBg[2];

    // prefetch k-tile 0
    #pragma unroll
    for (int p = 0; p < 4; p++)
        rA[p] = (arow[p] >= 0) ? *(const uint2*)(g_xn + (size_t)arow[p] * DIM + acol[p])
                               : make_uint2(0u, 0u);
    #pragma unroll
    for (int p = 0; p < 2; p++) {
        rBv[p] = *(const float4*)(Bv + (size_t)brow[p] * DIM + bcol[p]);
        rBg[p] = *(const float4*)(Bg + (size_t)brow[p] * DIM + bcol[p]);
    }

    for (int k0 = 0; k0 < DIM; k0 += 32) {
        #pragma unroll
        for (int p = 0; p < 4; p++) {
            unsigned* pA = &sA[arowi[p] * SW + (acol[p] >> 1)];
            pA[0] = rA[p].x; pA[1] = rA[p].y;          // already bf16 pairs
        }
        #pragma unroll
        for (int p = 0; p < 2; p++) {
            unsigned* pV = &sBv[brow[p] * SW + (bcol[p] >> 1)];
            pV[0] = pk(rBv[p].x, rBv[p].y); pV[1] = pk(rBv[p].z, rBv[p].w);
            unsigned* pG = &sBg[brow[p] * SW + (bcol[p] >> 1)];
            pG[0] = pk(rBg[p].x, rBg[p].y); pG[1] = pk(rBg[p].z, rBg[p].w);
        }
        __syncthreads();

        const int kn = k0 + 32;
        if (kn < DIM) {
            #pragma unroll
            for (int p = 0; p < 4; p++)
                rA[p] = (arow[p] >= 0) ? *(const uint2*)(g_xn + (size_t)arow[p] * DIM + kn + acol[p])
                                       : make_uint2(0u, 0u);
            #pragma unroll
            for (int p = 0; p < 2; p++) {
                rBv[p] = *(const float4*)(Bv + (size_t)brow[p] * DIM + kn + bcol[p]);
                rBg[p] = *(const float4*)(Bg + (size_t)brow[p] * DIM + kn + bcol[p]);
            }
        }

        #pragma unroll
        for (int ks = 0; ks < 2; ks++) {
            const int kb = ks * 8;
            unsigned a[2][4];
            #pragma unroll
            for (int sm = 0; sm < 2; sm++) {
                int rb = wm * 32 + sm * 16;
                a[sm][0] = sA[(rb + g    ) * SW + kb + l    ];
                a[sm][1] = sA[(rb + g + 8) * SW + kb + l    ];
                a[sm][2] = sA[(rb + g    ) * SW + kb + l + 4];
                a[sm][3] = sA[(rb + g + 8) * SW + kb + l + 4];
            }
            #pragma unroll
            for (int sn = 0; sn < 4; sn++) {
                int cb = wn * 32 + sn * 8;
                unsigned fv[2], fg[2];
                fv[0] = sBv[(cb + g) * SW + kb + l    ];
                fv[1] = sBv[(cb + g) * SW + kb + l + 4];
                fg[0] = sBg[(cb + g) * SW + kb + l    ];
                fg[1] = sBg[(cb + g) * SW + kb + l + 4];
                mma16(accv[0][sn], a[0], fv);
                mma16(accv[1][sn], a[1], fv);
                mma16(accg[0][sn], a[0], fg);
                mma16(accg[1][sn], a[1], fg);
            }
        }
        __syncthreads();
    }

    // epilogue: h = val * silu(gate), store bf16
    #pragma unroll
    for (int sm = 0; sm < 2; sm++) {
        #pragma unroll
        for (int sn = 0; sn < 4; sn++) {
            #pragma unroll
            for (int c = 0; c < 4; c++) {
                int row = wm * 32 + sm * 16 + g + ((c >> 1) << 3);
                int col = wn * 32 + sn * 8 + (l << 1) + (c & 1);
                if (m0 + row < M) {
                    float v  = accv[sm][sn][c];
                    float gt = accg[sm][sn][c];
                    float h  = v * (gt / (1.f + __expf(-gt)));
                    g_hact[(size_t)(base + m0 + row) * HID + jt * 64 + col] = __float2bfloat16(h);
                }
            }
        }
    }
}

// ---------------- kernel 5: grouped down-GEMM ------------------------------
// Tile: 128 rows x 64 cols, 256 threads, K-tile 32 over HID.
__global__ void __launch_bounds__(256) down_kernel(const float* __restrict__ w_down) {
    const int e    = blockIdx.z;
    const int M    = g_cnt[e];
    const int m0   = blockIdx.x * 128;
    if (m0 >= M) return;
    const int base = g_off[e];
    const int jt   = blockIdx.y;                  // 0 .. DIM/64-1

    __shared__ unsigned sA[128 * SW];
    __shared__ unsigned sB[ 64 * SW];

    const int tid  = threadIdx.x;
    const int lane = tid & 31;
    const int warp = tid >> 5;
    const int wm = warp >> 1, wn = warp & 1;
    const int g = lane >> 2, l = lane & 3;

    const float* Bp = w_down + (size_t)e * DIM * HID + (size_t)(jt * 64) * HID;
    const __nv_bfloat16* Ap = g_hact + (size_t)(base + m0) * HID;
    const int mrem = M - m0;

    int arow[4], acol[4];
    #pragma unroll
    for (int p = 0; p < 4; p++) {
        int idx = p * 256 + tid;
        arow[p] = idx >> 3;
        acol[p] = (idx & 7) << 2;
    }
    int brow[2], bcol[2];
    #pragma unroll
    for (int p = 0; p < 2; p++) {
        int idx = p * 256 + tid;
        brow[p] = idx >> 3;
        bcol[p] = (idx & 7) << 2;
    }

    float acc[2][4][4] = {};
    uint2  rA[4];
    float4 rB[2];

    #pragma unroll
    for (int p = 0; p < 4; p++)
        rA[p] = (arow[p] < mrem) ? *(const uint2*)(Ap + (size_t)arow[p] * HID + acol[p])
                                 : make_uint2(0u, 0u);
    #pragma unroll
    for (int p = 0; p < 2; p++)
        rB[p] = *(const float4*)(Bp + (size_t)brow[p] * HID + bcol[p]);

    for (int k0 = 0; k0 < HID; k0 += 32) {
        #pragma unroll
        for (int p = 0; p < 4; p++) {
            unsigned* pA = &sA[arow[p] * SW + (acol[p] >> 1)];
            pA[0] = rA[p].x; pA[1] = rA[p].y;
        }
        #pragma unroll
        for (int p = 0; p < 2; p++) {
            unsigned* pB = &sB[brow[p] * SW + (bcol[p] >> 1)];
            pB[0] = pk(rB[p].x, rB[p].y); pB[1] = pk(rB[p].z, rB[p].w);
        }
        __syncthreads();

        const int kn = k0 + 32;
        if (kn < HID) {
            #pragma unroll
            for (int p = 0; p < 4; p++)
                rA[p] = (arow[p] < mrem) ? *(const uint2*)(Ap + (size_t)arow[p] * HID + kn + acol[p])
                                         : make_uint2(0u, 0u);
            #pragma unroll
            for (int p = 0; p < 2; p++)
                rB[p] = *(const float4*)(Bp + (size_t)brow[p] * HID + kn + bcol[p]);
        }

        #pragma unroll
        for (int ks = 0; ks < 2; ks++) {
            const int kb = ks * 8;
            unsigned a[2][4];
            #pragma unroll
            for (int sm = 0; sm < 2; sm++) {
                int rb = wm * 32 + sm * 16;
                a[sm][0] = sA[(rb + g    ) * SW + kb + l    ];
                a[sm][1] = sA[(rb + g + 8) * SW + kb + l    ];
                a[sm][2] = sA[(rb + g    ) * SW + kb + l + 4];
                a[sm][3] = sA[(rb + g + 8) * SW + kb + l + 4];
            }
            #pragma unroll
            for (int sn = 0; sn < 4; sn++) {
                int cb = wn * 32 + sn * 8;
                unsigned fb[2];
                fb[0] = sB[(cb + g) * SW + kb + l    ];
                fb[1] = sB[(cb + g) * SW + kb + l + 4];
                mma16(acc[0][sn], a[0], fb);
                mma16(acc[1][sn], a[1], fb);
            }
        }
        __syncthreads();
    }

    #pragma unroll
    for (int sm = 0; sm < 2; sm++) {
        #pragma unroll
        for (int sn = 0; sn < 4; sn++) {
            #pragma unroll
            for (int c = 0; c < 4; c++) {
                int row = wm * 32 + sm * 16 + g + ((c >> 1) << 3);
                int col = wn * 32 + sn * 8 + (l << 1) + (c & 1);
                if (m0 + row < M) {
                    g_y[(size_t)(base + m0 + row) * DIM + jt * 64 + col] = acc[sm][sn][c];
                }
            }
        }
    }
}

// ---------------- kernel 6: combine + skip ---------------------------------
__global__ void __launch_bounds__(256) combine_kernel(
    const float* __restrict__ x, float* __restrict__ out)
{
    const int t = blockIdx.x;
    const int r0 = g_rowof[2 * t + 0];
    const int r1 = g_rowof[2 * t + 1];
    const float c0 = g_coef[2 * t + 0];
    const float c1 = g_coef[2 * t + 1];
    const int i = threadIdx.x * 4;

    float4 xv = *(const float4*)(x   + (size_t)t  * DIM + i);
    float4 y0 = *(const float4*)(g_y + (size_t)r0 * DIM + i);
    float4 y1 = *(const float4*)(g_y + (size_t)r1 * DIM + i);
    float4 o;
    o.x = xv.x + c0 * y0.x + c1 * y1.x;
    o.y = xv.y + c0 * y0.y + c1 * y1.y;
    o.z = xv.z + c0 * y0.z + c1 * y1.z;
    o.w = xv.w + c0 * y0.w + c1 * y1.w;
    *(float4*)(out + (size_t)t * DIM + i) = o;
}

// ---------------- launch ---------------------------------------------------
extern "C" void kernel_launch(void* const* d_in, const int* in_sizes, int n_in,
                              void* d_out, int out_size) {
    (void)in_sizes; (void)n_in; (void)out_size;
    const float* x     = (const float*)d_in[0];   // [2,2048,1024] -> [4096,1024]
    const float* scale = (const float*)d_in[1];   // [1024]
    const float* wr    = (const float*)d_in[2];   // [8,1024]
    const float* wup   = (const float*)d_in[3];   // [8,5632,1024]
    const float* wdn   = (const float*)d_in[4];   // [8,1024,2816]
    float* out = (float*)d_out;

    zero_cnt_kernel<<<1, 32>>>();
    phase1_kernel<<<TOK, 256>>>(x, scale, wr);
    offsets_kernel<<<1, 32>>>();
    scatter_kernel<<<(TOK + 255) / 256, 256>>>();
    up_kernel<<<dim3(TOK / 128, HID / 64, NEXP), 256>>>(wup);
    down_kernel<<<dim3(TOK / 128, DIM / 64, NEXP), 256>>>(wdn);
    combine_kernel<<<TOK, 256>>>(x, out);
}